// round 14
// baseline (speedup 1.0000x reference)
#include <cuda_runtime.h>
#include <cuda_fp16.h>
#include <stdint.h>

// TriangleMultiplicativeUpdate — persistent single-launch kernel, round 13.
// mma.sync m16n8k16 fp16 (fp32 accum), single-pass fp16 weights resident in
// smem (converted in-kernel). 128-ROW tiles (warp tile 32x32, 4x4 warps):
// B-fragment ldmatrix and barrier costs amortize over 2x rows (-27% LDSM,
// 4 barriers/128 rows vs 6). Product reassociated as
//   x = [(bp+b)m sig(bg+b)] * [(ap+b)m] * [sig(ag+b)]
// so only one 32-reg running array is ever live with a 64-reg pair.

#define NT 512

#define OFF_ZN   0u                 // zn/xn: 128 x 256B fp16, swizzled
#define OFF_W0   32768u             // 6 weight slots, 32768B each, swizzled
#define WSLOT(i) (OFF_W0 + (uint32_t)(i) * 32768u)
#define OFF_SB   229376u            // 6 x 128 __half biases
#define OFF_MK   230912u            // 128 __half mask
#define OFF_RED  231168u            // 128 x 2 float (atomic LN_out partials)
#define SMEM_BYTES 232192

__device__ __forceinline__ uint32_t s2u(const void* p) {
    uint32_t a;
    asm("{ .reg .u64 t; cvta.to.shared.u64 t, %1; cvt.u32.u64 %0, t; }" : "=r"(a) : "l"(p));
    return a;
}
__device__ __forceinline__ uint32_t f16x2(float lo, float hi) {
    uint32_t r;
    asm("cvt.rn.f16x2.f32 %0, %1, %2;" : "=r"(r) : "f"(hi), "f"(lo));
    return r;
}

#define LDSM4(r, a) \
    asm volatile("ldmatrix.sync.aligned.m8n8.x4.shared.b16 {%0,%1,%2,%3}, [%4];" \
        : "=r"((r)[0]), "=r"((r)[1]), "=r"((r)[2]), "=r"((r)[3]) : "r"(a))

#define MMAOP(d, a, b0, b1) \
    asm volatile("mma.sync.aligned.m16n8k16.row.col.f32.f16.f16.f32 " \
        "{%0,%1,%2,%3}, {%4,%5,%6,%7}, {%8,%9}, {%0,%1,%2,%3};" \
        : "+f"((d)[0]), "+f"((d)[1]), "+f"((d)[2]), "+f"((d)[3]) \
        : "r"((a)[0]), "r"((a)[1]), "r"((a)[2]), "r"((a)[3]), "r"(b0), "r"(b1))

__device__ __forceinline__ float sigm(float x) { return 1.0f / (1.0f + __expf(-x)); }

// single pass, 32-row A: acc[32] += A(32x128) @ W^T (32 cols)
__device__ __forceinline__ void mm1(float* acc, uint32_t azn, uint32_t l16a, uint32_t axv,
                                    uint32_t wb, uint32_t l16, uint32_t xv) {
#pragma unroll
    for (int k = 0; k < 8; k++) {
        uint32_t ko = (uint32_t)k * 32u;
        uint32_t offa = (ko + l16a) ^ axv;
        uint32_t offb = (ko + l16) ^ xv;
        uint32_t A0[4], A1[4], B0[4], B1[4];
        LDSM4(A0, azn + offa);
        LDSM4(A1, azn + 4096u + offa);
        LDSM4(B0, wb + offb);
        LDSM4(B1, wb + offb + 4096u);
        MMAOP(acc + 0,  A0, B0[0], B0[1]); MMAOP(acc + 4,  A0, B0[2], B0[3]);
        MMAOP(acc + 8,  A0, B1[0], B1[1]); MMAOP(acc + 12, A0, B1[2], B1[3]);
        MMAOP(acc + 16, A1, B0[0], B0[1]); MMAOP(acc + 20, A1, B0[2], B0[3]);
        MMAOP(acc + 24, A1, B1[0], B1[1]); MMAOP(acc + 28, A1, B1[2], B1[3]);
    }
}

// paired pass, 32-row A: accP += A@Wp^T, accG += A@Wg^T (A loaded once)
__device__ __forceinline__ void mm_pair(float* accP, float* accG,
                                        uint32_t azn, uint32_t l16a, uint32_t axv,
                                        uint32_t wpb, uint32_t wgb,
                                        uint32_t l16, uint32_t xv) {
#pragma unroll
    for (int k = 0; k < 8; k++) {
        uint32_t ko = (uint32_t)k * 32u;
        uint32_t offa = (ko + l16a) ^ axv;
        uint32_t offb = (ko + l16) ^ xv;
        uint32_t A0[4], A1[4], P0[4], P1[4], G0[4], G1[4];
        LDSM4(A0, azn + offa);
        LDSM4(A1, azn + 4096u + offa);
        LDSM4(P0, wpb + offb); LDSM4(P1, wpb + offb + 4096u);
        LDSM4(G0, wgb + offb); LDSM4(G1, wgb + offb + 4096u);
        MMAOP(accP + 0,  A0, P0[0], P0[1]); MMAOP(accP + 4,  A0, P0[2], P0[3]);
        MMAOP(accP + 8,  A0, P1[0], P1[1]); MMAOP(accP + 12, A0, P1[2], P1[3]);
        MMAOP(accP + 16, A1, P0[0], P0[1]); MMAOP(accP + 20, A1, P0[2], P0[3]);
        MMAOP(accP + 24, A1, P1[0], P1[1]); MMAOP(accP + 28, A1, P1[2], P1[3]);
        MMAOP(accG + 0,  A0, G0[0], G0[1]); MMAOP(accG + 4,  A0, G0[2], G0[3]);
        MMAOP(accG + 8,  A0, G1[0], G1[1]); MMAOP(accG + 12, A0, G1[2], G1[3]);
        MMAOP(accG + 16, A1, G0[0], G0[1]); MMAOP(accG + 20, A1, G0[2], G0[3]);
        MMAOP(accG + 24, A1, G1[0], G1[1]); MMAOP(accG + 28, A1, G1[2], G1[3]);
    }
}

__global__ void __launch_bounds__(NT, 1)
tmu_kernel(const float* __restrict__ z, const float* __restrict__ mask,
           const float* __restrict__ w_ap, const float* __restrict__ b_ap,
           const float* __restrict__ w_bp, const float* __restrict__ b_bp,
           const float* __restrict__ w_ag, const float* __restrict__ b_ag,
           const float* __restrict__ w_bg, const float* __restrict__ b_bg,
           const float* __restrict__ w_g,  const float* __restrict__ b_g,
           const float* __restrict__ w_z,  const float* __restrict__ b_z,
           const float* __restrict__ ln_in_w,  const float* __restrict__ ln_in_b,
           const float* __restrict__ ln_out_w, const float* __restrict__ ln_out_b,
           float* __restrict__ out, int ntiles) {
    extern __shared__ char sm[];
    const uint32_t smb = s2u(sm);
    const int t = threadIdx.x;
    const int w = t >> 5, lid = t & 31;
    const int quad = lid >> 2, qt = lid & 3;
    const int wr = (w & 3) * 32;          // 4 row-warps x 32 rows
    const int wc = (w >> 2) * 32;         // 4 col-warps x 32 cols
    // this thread's 4 output rows
    const int r00 = wr + quad, r01 = r00 + 8, r10 = r00 + 16, r11 = r00 + 24;

    __half* bh  = (__half*)(sm + OFF_SB);
    __half* mkh = (__half*)(sm + OFF_MK);
    float*  red = (float*)(sm + OFF_RED);   // [128][2] sum, sumsq (atomics)

    // ---- in-kernel weight prep: fp32 global -> fp16 swizzled smem ----
#pragma unroll
    for (int m = 0; m < 6; m++) {
        const float* wp = (m == 0) ? w_ap : (m == 1) ? w_ag : (m == 2) ? w_bp :
                          (m == 3) ? w_bg : (m == 4) ? w_g : w_z;
        const float4* src = (const float4*)wp;
#pragma unroll
        for (int i = 0; i < 4; i++) {
            int cid = t + i * NT;              // 2048 16B-dst chunks
            int n = cid >> 4, c8 = cid & 15;
            float4 f0 = __ldg(src + n * 32 + c8 * 2);
            float4 f1 = __ldg(src + n * 32 + c8 * 2 + 1);
            uint4 hv = make_uint4(f16x2(f0.x, f0.y), f16x2(f0.z, f0.w),
                                  f16x2(f1.x, f1.y), f16x2(f1.z, f1.w));
            uint32_t off = WSLOT(m) + (uint32_t)n * 256u +
                           (((uint32_t)c8 * 16u) ^ (((uint32_t)n & 7u) << 4));
            *(uint4*)(sm + off) = hv;
        }
    }
    if (t < 128) {
        bh[t]       = __float2half(__ldg(b_ap + t));
        bh[128 + t] = __float2half(__ldg(b_ag + t));
        bh[256 + t] = __float2half(__ldg(b_bp + t));
        bh[384 + t] = __float2half(__ldg(b_bg + t));
        bh[512 + t] = __float2half(__ldg(b_g + t));
        bh[640 + t] = __float2half(__ldg(b_z + t));
    }
    if (t < 256) red[t] = 0.f;

    // per-warp/lane ldmatrix constants
    const uint32_t arow = (uint32_t)(wr + (lid & 15)) * 256u;   // mg0; mg1 = +4096
    const uint32_t l16a = (uint32_t)(lid >> 4) * 16u;
    const uint32_t axv = (uint32_t)(lid & 7) << 4;
    const int n_lane = wc + (lid & 7) + ((lid >> 4) << 3);
    const uint32_t l16 = (uint32_t)((lid >> 3) & 1) * 16u;
    const uint32_t xv = (uint32_t)(n_lane & 7) << 4;
    const uint32_t wnl = (uint32_t)n_lane * 256u;
    const uint32_t W0 = smb + WSLOT(0) + wnl, W1 = smb + WSLOT(1) + wnl;
    const uint32_t W2 = smb + WSLOT(2) + wnl, W3 = smb + WSLOT(3) + wnl;
    const uint32_t W4 = smb + WSLOT(4) + wnl, W5 = smb + WSLOT(5) + wnl;
    const uint32_t azn = smb + OFF_ZN + arow;

    for (int tile = blockIdx.x; tile < ntiles; tile += gridDim.x) {
        const size_t row0 = (size_t)tile * 128;

        // L2 prefetch of next z tile (64KB: 512 thr x 128B)
        if (tile + gridDim.x < ntiles) {
            const char* zp = (const char*)(z + (size_t)(tile + gridDim.x) * 128 * 128) + t * 128;
            asm volatile("prefetch.global.L2 [%0];" :: "l"(zp));
            asm volatile("prefetch.global.L2 [%0];" :: "l"(zp + 64));
        }

        // ---- LN_in: 4 threads/row over 128 rows; write zn fp16 swizzled ----
        {
            const int r = t >> 2, q = t & 3;
            const uint32_t rxv = (uint32_t)(r & 7) << 4;
            const float* zr = z + (row0 + r) * 128 + q * 32;
            float v[32], s = 0.f, s2 = 0.f;
#pragma unroll
            for (int i = 0; i < 8; i++) {
                float4 f = __ldg((const float4*)(zr + 4 * i));
                v[4*i] = f.x; v[4*i+1] = f.y; v[4*i+2] = f.z; v[4*i+3] = f.w;
                s += f.x + f.y + f.z + f.w;
                s2 += f.x*f.x + f.y*f.y + f.z*f.z + f.w*f.w;
            }
            s  += __shfl_xor_sync(~0u, s, 1);  s  += __shfl_xor_sync(~0u, s, 2);
            s2 += __shfl_xor_sync(~0u, s2, 1); s2 += __shfl_xor_sync(~0u, s2, 2);
            float mu = s * (1.f / 128);
            float rstd = rsqrtf(fmaxf(s2 * (1.f / 128) - mu * mu, 0.f) + 1e-5f);
#pragma unroll
            for (int j = 0; j < 4; j++) {
                uint32_t h[4];
#pragma unroll
                for (int i = 0; i < 4; i++) {
                    int c = q * 32 + j * 8 + i * 2;
                    float f0 = (v[j*8+i*2]   - mu) * rstd * __ldg(ln_in_w + c)   + __ldg(ln_in_b + c);
                    float f1 = (v[j*8+i*2+1] - mu) * rstd * __ldg(ln_in_w + c+1) + __ldg(ln_in_b + c+1);
                    h[i] = f16x2(f0, f1);
                }
                uint32_t o = (((uint32_t)(q * 4 + j)) * 16u) ^ rxv;
                *(uint4*)(sm + OFF_ZN + (uint32_t)r * 256u + o) = make_uint4(h[0], h[1], h[2], h[3]);
            }
            if (q == 0) mkh[r] = __float2half(__ldg(mask + row0 + r));
        }
        __syncthreads();                       // S1: zn + mk visible; red zeroed

        float x[32], acc[32], accG[32];
        const float m00 = __half2float(mkh[r00]), m01 = __half2float(mkh[r01]);
        const float m10 = __half2float(mkh[r10]), m11 = __half2float(mkh[r11]);

        // ===== pass1 (pair): x = (zn@w_bp^T + b)*m * sig(zn@w_bg^T + b) =====
#pragma unroll
        for (int e = 0; e < 32; e++) { x[e] = 0.f; accG[e] = 0.f; }
        mm_pair(x, accG, azn, l16a, axv, W2, W3, l16, xv);
#pragma unroll
        for (int mg = 0; mg < 2; mg++) {
            float ma = mg ? m10 : m00, mb = mg ? m11 : m01;
#pragma unroll
            for (int nb = 0; nb < 4; nb++) {
                int e = mg * 16 + nb * 4, col = wc + nb * 8 + qt * 2;
                float2 bp = __half22float2(*(__half2*)(bh + 256 + col));
                float2 bg = __half22float2(*(__half2*)(bh + 384 + col));
                x[e]   = (x[e]   + bp.x) * ma * sigm(accG[e]   + bg.x);
                x[e+1] = (x[e+1] + bp.y) * ma * sigm(accG[e+1] + bg.y);
                x[e+2] = (x[e+2] + bp.x) * mb * sigm(accG[e+2] + bg.x);
                x[e+3] = (x[e+3] + bp.y) * mb * sigm(accG[e+3] + bg.y);
            }
        }

        // ===== pass2 (single, ap): x *= (zn@w_ap^T + b)*m =====
#pragma unroll
        for (int e = 0; e < 32; e++) acc[e] = 0.f;
        mm1(acc, azn, l16a, axv, W0, l16, xv);
#pragma unroll
        for (int mg = 0; mg < 2; mg++) {
            float ma = mg ? m10 : m00, mb = mg ? m11 : m01;
#pragma unroll
            for (int nb = 0; nb < 4; nb++) {
                int e = mg * 16 + nb * 4, col = wc + nb * 8 + qt * 2;
                float2 bp = __half22float2(*(__half2*)(bh + col));
                x[e]   *= (acc[e]   + bp.x) * ma;
                x[e+1] *= (acc[e+1] + bp.y) * ma;
                x[e+2] *= (acc[e+2] + bp.x) * mb;
                x[e+3] *= (acc[e+3] + bp.y) * mb;
            }
        }

        // ===== pass3 (single, ag): x *= sig(...); LN partial atomics =====
#pragma unroll
        for (int e = 0; e < 32; e++) acc[e] = 0.f;
        mm1(acc, azn, l16a, axv, W1, l16, xv);
        {
            float sA = 0.f, sA2 = 0.f, sB = 0.f, sB2 = 0.f;
            float sC = 0.f, sC2 = 0.f, sD = 0.f, sD2 = 0.f;
#pragma unroll
            for (int nb = 0; nb < 4; nb++) {
                int col = wc + nb * 8 + qt * 2;
                float2 bg = __half22float2(*(__half2*)(bh + 128 + col));
                int e = nb * 4;
                x[e]    *= sigm(acc[e]    + bg.x);
                x[e+1]  *= sigm(acc[e+1]  + bg.y);
                x[e+2]  *= sigm(acc[e+2]  + bg.x);
                x[e+3]  *= sigm(acc[e+3]  + bg.y);
                sA += x[e] + x[e+1];   sA2 += x[e]*x[e] + x[e+1]*x[e+1];
                sB += x[e+2] + x[e+3]; sB2 += x[e+2]*x[e+2] + x[e+3]*x[e+3];
                e += 16;
                x[e]    *= sigm(acc[e]    + bg.x);
                x[e+1]  *= sigm(acc[e+1]  + bg.y);
                x[e+2]  *= sigm(acc[e+2]  + bg.x);
                x[e+3]  *= sigm(acc[e+3]  + bg.y);
                sC += x[e] + x[e+1];   sC2 += x[e]*x[e] + x[e+1]*x[e+1];
                sD += x[e+2] + x[e+3]; sD2 += x[e+2]*x[e+2] + x[e+3]*x[e+3];
            }
            sA += __shfl_xor_sync(~0u, sA, 1);  sA += __shfl_xor_sync(~0u, sA, 2);
            sA2 += __shfl_xor_sync(~0u, sA2, 1); sA2 += __shfl_xor_sync(~0u, sA2, 2);
            sB += __shfl_xor_sync(~0u, sB, 1);  sB += __shfl_xor_sync(~0u, sB, 2);
            sB2 += __shfl_xor_sync(~0u, sB2, 1); sB2 += __shfl_xor_sync(~0u, sB2, 2);
            sC += __shfl_xor_sync(~0u, sC, 1);  sC += __shfl_xor_sync(~0u, sC, 2);
            sC2 += __shfl_xor_sync(~0u, sC2, 1); sC2 += __shfl_xor_sync(~0u, sC2, 2);
            sD += __shfl_xor_sync(~0u, sD, 1);  sD += __shfl_xor_sync(~0u, sD, 2);
            sD2 += __shfl_xor_sync(~0u, sD2, 1); sD2 += __shfl_xor_sync(~0u, sD2, 2);
            if (qt == 0) {
                atomicAdd(red + 2*r00, sA); atomicAdd(red + 2*r00 + 1, sA2);
                atomicAdd(red + 2*r01, sB); atomicAdd(red + 2*r01 + 1, sB2);
                atomicAdd(red + 2*r10, sC); atomicAdd(red + 2*r10 + 1, sC2);
                atomicAdd(red + 2*r11, sD); atomicAdd(red + 2*r11 + 1, sD2);
            }
        }

        // ===== pass4 (single, g): gate = sig(zn @ w_g^T + b_g) -> accG =====
#pragma unroll
        for (int e = 0; e < 32; e++) accG[e] = 0.f;
        mm1(accG, azn, l16a, axv, W4, l16, xv);
#pragma unroll
        for (int mg = 0; mg < 2; mg++) {
#pragma unroll
            for (int nb = 0; nb < 4; nb++) {
                int e = mg * 16 + nb * 4, col = wc + nb * 8 + qt * 2;
                float2 bg = __half22float2(*(__half2*)(bh + 512 + col));
                accG[e]   = sigm(accG[e]   + bg.x);
                accG[e+1] = sigm(accG[e+1] + bg.y);
                accG[e+2] = sigm(accG[e+2] + bg.x);
                accG[e+3] = sigm(accG[e+3] + bg.y);
            }
        }
        __syncthreads();                       // S2: atomics drained; zn reads done

        // LN_out stats + xn -> zn (fp16, swizzled)
        {
            float muv[4], rsv[4];
            const int rr[4] = {r00, r01, r10, r11};
#pragma unroll
            for (int i = 0; i < 4; i++) {
                float s = red[2*rr[i]], s2 = red[2*rr[i]+1];
                muv[i] = s * (1.f / 128);
                rsv[i] = rsqrtf(fmaxf(s2 * (1.f / 128) - muv[i]*muv[i], 0.f) + 1e-5f);
            }
#pragma unroll
            for (int mg = 0; mg < 2; mg++) {
#pragma unroll
                for (int nb = 0; nb < 4; nb++) {
                    int e = mg * 16 + nb * 4, col = wc + nb * 8 + qt * 2;
                    float lw0 = __ldg(ln_out_w + col), lw1 = __ldg(ln_out_w + col + 1);
                    float lb0 = __ldg(ln_out_b + col), lb1 = __ldg(ln_out_b + col + 1);
                    int ia = mg * 2, ib = mg * 2 + 1;
                    float v0 = (x[e]   - muv[ia]) * rsv[ia] * lw0 + lb0;
                    float v1 = (x[e+1] - muv[ia]) * rsv[ia] * lw1 + lb1;
                    float v2 = (x[e+2] - muv[ib]) * rsv[ib] * lw0 + lb0;
                    float v3 = (x[e+3] - muv[ib]) * rsv[ib] * lw1 + lb1;
                    uint32_t cb = (uint32_t)col * 2u;
                    int ra = mg ? r10 : r00, rb = mg ? r11 : r01;
                    *(uint32_t*)(sm + OFF_ZN + (uint32_t)ra * 256u + (cb ^ ((uint32_t)(ra & 7) << 4))) = f16x2(v0, v1);
                    *(uint32_t*)(sm + OFF_ZN + (uint32_t)rb * 256u + (cb ^ ((uint32_t)(rb & 7) << 4))) = f16x2(v2, v3);
                }
            }
        }
        __syncthreads();                       // S3: xn visible; red fully read
        if (t < 256) red[t] = 0.f;             // re-arm stats

        // ===== pass5 (single, z on xn): out = (xn @ w_z^T + b_z) * gate =====
#pragma unroll
        for (int e = 0; e < 32; e++) acc[e] = 0.f;
        mm1(acc, azn, l16a, axv, W5, l16, xv);
#pragma unroll
        for (int mg = 0; mg < 2; mg++) {
            int ra = mg ? r10 : r00, rb = mg ? r11 : r01;
            float* oa = out + (row0 + ra) * 128;
            float* ob = out + (row0 + rb) * 128;
#pragma unroll
            for (int nb = 0; nb < 4; nb++) {
                int e = mg * 16 + nb * 4, col = wc + nb * 8 + qt * 2;
                float2 bz = __half22float2(*(__half2*)(bh + 640 + col));
                float2 u, v2;
                u.x  = (acc[e]   + bz.x) * accG[e];
                u.y  = (acc[e+1] + bz.y) * accG[e+1];
                v2.x = (acc[e+2] + bz.x) * accG[e+2];
                v2.y = (acc[e+3] + bz.y) * accG[e+3];
                *(float2*)(oa + col) = u;
                *(float2*)(ob + col) = v2;
            }
        }
        __syncthreads();                       // S4: zn free; red zero visible
    }
}

extern "C" void kernel_launch(void* const* d_in, const int* in_sizes, int n_in,
                              void* d_out, int out_size) {
    const float* z        = (const float*)d_in[0];
    const float* mask     = (const float*)d_in[1];
    const float* w_ap     = (const float*)d_in[2];
    const float* b_ap     = (const float*)d_in[3];
    const float* w_bp     = (const float*)d_in[4];
    const float* b_bp     = (const float*)d_in[5];
    const float* w_ag     = (const float*)d_in[6];
    const float* b_ag     = (const float*)d_in[7];
    const float* w_bg     = (const float*)d_in[8];
    const float* b_bg     = (const float*)d_in[9];
    const float* w_g      = (const float*)d_in[10];
    const float* b_g      = (const float*)d_in[11];
    const float* w_z      = (const float*)d_in[12];
    const float* b_z      = (const float*)d_in[13];
    const float* ln_in_w  = (const float*)d_in[14];
    const float* ln_in_b  = (const float*)d_in[15];
    const float* ln_out_w = (const float*)d_in[16];
    const float* ln_out_b = (const float*)d_in[17];
    float* out = (float*)d_out;

    const int rows = in_sizes[1];      // B*N*N
    const int ntiles = rows / 128;     // 1152

    static int nsm = 0;
    if (!nsm) {
        cudaFuncSetAttribute(tmu_kernel, cudaFuncAttributeMaxDynamicSharedMemorySize, SMEM_BYTES);
        if (cudaDeviceGetAttribute(&nsm, cudaDevAttrMultiProcessorCount, 0) != cudaSuccess || nsm <= 0)
            nsm = 148;
    }
    int grid = nsm < ntiles ? nsm : ntiles;

    tmu_kernel<<<grid, NT, SMEM_BYTES>>>(z, mask,
                                         w_ap, b_ap, w_bp, b_bp,
                                         w_ag, b_ag, w_bg, b_bg,
                                         w_g, b_g, w_z, b_z,
                                         ln_in_w, ln_in_b, ln_out_w, ln_out_b,
                                         out, ntiles);
}

// round 15
// speedup vs baseline: 1.0725x; 1.0725x over previous
#include <cuda_runtime.h>
#include <cuda_fp16.h>
#include <stdint.h>

// TriangleMultiplicativeUpdate — persistent single-launch kernel, round 14.
// R12 chassis (all six fp16 weights resident in smem, in-kernel conversion,
// double-buffered zn, 64-row tiles, 16x(16x32) warp grid) with ALL FIVE
// zn-matmuls fused into ONE quint pass: A fragments ldmatrix'd once per
// k-step feed 10 B fragments and 5 accumulator sets (20 MMAs). LDSM.x4 per
// warp per tile drops 144 -> 112 (-22% smem read bytes, the largest pool).

#define NT 512

#define OFF_ZN   0u                 // zn/xn: 2 x (64 x 256B fp16, swizzled)
#define OFF_W0   32768u             // 6 weight slots, 32768B each, swizzled
#define WSLOT(i) (OFF_W0 + (uint32_t)(i) * 32768u)
#define OFF_SB   229376u            // 8 x 128 __half (biases, ln_out w/b)
#define OFF_MK   231424u            // 2 x 64 __half (mask per buffer)
#define OFF_RED  231680u            // 64 x float2 (LN_out partials, atomics)
#define SMEM_BYTES 232192

__device__ __forceinline__ uint32_t s2u(const void* p) {
    uint32_t a;
    asm("{ .reg .u64 t; cvta.to.shared.u64 t, %1; cvt.u32.u64 %0, t; }" : "=r"(a) : "l"(p));
    return a;
}
__device__ __forceinline__ uint32_t f16x2(float lo, float hi) {
    uint32_t r;
    asm("cvt.rn.f16x2.f32 %0, %1, %2;" : "=r"(r) : "f"(hi), "f"(lo));
    return r;
}

#define LDSM4(r, a) \
    asm volatile("ldmatrix.sync.aligned.m8n8.x4.shared.b16 {%0,%1,%2,%3}, [%4];" \
        : "=r"((r)[0]), "=r"((r)[1]), "=r"((r)[2]), "=r"((r)[3]) : "r"(a))

#define MMAOP(d, a, b0, b1) \
    asm volatile("mma.sync.aligned.m16n8k16.row.col.f32.f16.f16.f32 " \
        "{%0,%1,%2,%3}, {%4,%5,%6,%7}, {%8,%9}, {%0,%1,%2,%3};" \
        : "+f"((d)[0]), "+f"((d)[1]), "+f"((d)[2]), "+f"((d)[3]) \
        : "r"((a)[0]), "r"((a)[1]), "r"((a)[2]), "r"((a)[3]), "r"(b0), "r"(b1))

__device__ __forceinline__ float sigm(float x) { return 1.0f / (1.0f + __expf(-x)); }

// single pass: acc[16] += A(16x128) @ W^T (32 cols); swizzled operands.
__device__ __forceinline__ void mm1(float* acc, uint32_t azn, uint32_t l16a, uint32_t axv,
                                    uint32_t wb, uint32_t l16, uint32_t xv) {
#pragma unroll
    for (int k = 0; k < 8; k++) {
        uint32_t ko = (uint32_t)k * 32u;
        uint32_t offa = (ko + l16a) ^ axv;
        uint32_t offb = (ko + l16) ^ xv;
        uint32_t A[4], B0[4], B1[4];
        LDSM4(A, azn + offa);
        LDSM4(B0, wb + offb);
        LDSM4(B1, wb + offb + 4096u);
        MMAOP(acc + 0,  A, B0[0], B0[1]); MMAOP(acc + 4,  A, B0[2], B0[3]);
        MMAOP(acc + 8,  A, B1[0], B1[1]); MMAOP(acc + 12, A, B1[2], B1[3]);
    }
}

// quint pass: 5 accumulator sets against 5 weights, A loaded ONCE per k-step.
__device__ __forceinline__ void mm_quint(float* a0, float* a1, float* a2,
                                         float* a3, float* a4,
                                         uint32_t azn, uint32_t l16a, uint32_t axv,
                                         uint32_t w0, uint32_t w1, uint32_t w2,
                                         uint32_t w3, uint32_t w4,
                                         uint32_t l16, uint32_t xv) {
#pragma unroll
    for (int k = 0; k < 8; k++) {
        uint32_t ko = (uint32_t)k * 32u;
        uint32_t offa = (ko + l16a) ^ axv;
        uint32_t offb = (ko + l16) ^ xv;
        uint32_t A[4];
        LDSM4(A, azn + offa);
        {
            uint32_t B0[4], B1[4];
            LDSM4(B0, w0 + offb); LDSM4(B1, w0 + offb + 4096u);
            MMAOP(a0 + 0,  A, B0[0], B0[1]); MMAOP(a0 + 4,  A, B0[2], B0[3]);
            MMAOP(a0 + 8,  A, B1[0], B1[1]); MMAOP(a0 + 12, A, B1[2], B1[3]);
        }
        {
            uint32_t B0[4], B1[4];
            LDSM4(B0, w1 + offb); LDSM4(B1, w1 + offb + 4096u);
            MMAOP(a1 + 0,  A, B0[0], B0[1]); MMAOP(a1 + 4,  A, B0[2], B0[3]);
            MMAOP(a1 + 8,  A, B1[0], B1[1]); MMAOP(a1 + 12, A, B1[2], B1[3]);
        }
        {
            uint32_t B0[4], B1[4];
            LDSM4(B0, w2 + offb); LDSM4(B1, w2 + offb + 4096u);
            MMAOP(a2 + 0,  A, B0[0], B0[1]); MMAOP(a2 + 4,  A, B0[2], B0[3]);
            MMAOP(a2 + 8,  A, B1[0], B1[1]); MMAOP(a2 + 12, A, B1[2], B1[3]);
        }
        {
            uint32_t B0[4], B1[4];
            LDSM4(B0, w3 + offb); LDSM4(B1, w3 + offb + 4096u);
            MMAOP(a3 + 0,  A, B0[0], B0[1]); MMAOP(a3 + 4,  A, B0[2], B0[3]);
            MMAOP(a3 + 8,  A, B1[0], B1[1]); MMAOP(a3 + 12, A, B1[2], B1[3]);
        }
        {
            uint32_t B0[4], B1[4];
            LDSM4(B0, w4 + offb); LDSM4(B1, w4 + offb + 4096u);
            MMAOP(a4 + 0,  A, B0[0], B0[1]); MMAOP(a4 + 4,  A, B0[2], B0[3]);
            MMAOP(a4 + 8,  A, B1[0], B1[1]); MMAOP(a4 + 12, A, B1[2], B1[3]);
        }
    }
}

// LN_in for one 64-row tile into zn buffer `bufoff`; 8 threads/row.
__device__ __forceinline__ void ln_in_tile(char* sm, const float* z,
                                           const float* mask,
                                           const float* ln_in_w, const float* ln_in_b,
                                           size_t row0, uint32_t bufoff,
                                           __half* mkh, int t) {
    const int r = t >> 3, q = t & 7;
    const uint32_t rxv = (uint32_t)(r & 7) << 4;
    const float* zr = z + (row0 + r) * 128 + q * 16;
    float v[16], s = 0.f, s2 = 0.f;
#pragma unroll
    for (int i = 0; i < 4; i++) {
        float4 f = __ldg((const float4*)(zr + 4 * i));
        v[4*i] = f.x; v[4*i+1] = f.y; v[4*i+2] = f.z; v[4*i+3] = f.w;
        s += f.x + f.y + f.z + f.w;
        s2 += f.x*f.x + f.y*f.y + f.z*f.z + f.w*f.w;
    }
    s  += __shfl_xor_sync(~0u, s, 1);  s  += __shfl_xor_sync(~0u, s, 2);
    s  += __shfl_xor_sync(~0u, s, 4);
    s2 += __shfl_xor_sync(~0u, s2, 1); s2 += __shfl_xor_sync(~0u, s2, 2);
    s2 += __shfl_xor_sync(~0u, s2, 4);
    float mu = s * (1.f / 128);
    float rstd = rsqrtf(fmaxf(s2 * (1.f / 128) - mu * mu, 0.f) + 1e-5f);
#pragma unroll
    for (int j = 0; j < 2; j++) {
        uint32_t h[4];
#pragma unroll
        for (int i = 0; i < 4; i++) {
            int c = q * 16 + j * 8 + i * 2;
            float f0 = (v[j*8+i*2]   - mu) * rstd * __ldg(ln_in_w + c)   + __ldg(ln_in_b + c);
            float f1 = (v[j*8+i*2+1] - mu) * rstd * __ldg(ln_in_w + c+1) + __ldg(ln_in_b + c+1);
            h[i] = f16x2(f0, f1);
        }
        uint32_t o = ((uint32_t)(q * 2 + j) * 16u) ^ rxv;
        *(uint4*)(sm + OFF_ZN + bufoff + (uint32_t)r * 256u + o) =
            make_uint4(h[0], h[1], h[2], h[3]);
    }
    if (q == 0) mkh[r] = __float2half(__ldg(mask + row0 + r));
}

__global__ void __launch_bounds__(NT, 1)
tmu_kernel(const float* __restrict__ z, const float* __restrict__ mask,
           const float* __restrict__ w_ap, const float* __restrict__ b_ap,
           const float* __restrict__ w_bp, const float* __restrict__ b_bp,
           const float* __restrict__ w_ag, const float* __restrict__ b_ag,
           const float* __restrict__ w_bg, const float* __restrict__ b_bg,
           const float* __restrict__ w_g,  const float* __restrict__ b_g,
           const float* __restrict__ w_z,  const float* __restrict__ b_z,
           const float* __restrict__ ln_in_w,  const float* __restrict__ ln_in_b,
           const float* __restrict__ ln_out_w, const float* __restrict__ ln_out_b,
           float* __restrict__ out, int ntiles) {
    extern __shared__ char sm[];
    const uint32_t smb = s2u(sm);
    const int t = threadIdx.x;
    const int w = t >> 5, lid = t & 31;
    const int quad = lid >> 2, qt = lid & 3;
    const int wr = (w & 3) * 16;
    const int wc = (w >> 2) * 32;
    const int r0 = wr + quad, r1 = r0 + 8;

    __half* bh  = (__half*)(sm + OFF_SB);
    __half* mkh = (__half*)(sm + OFF_MK);
    float*  red = (float*)(sm + OFF_RED);    // [64][2] sum, sumsq

    // ---- in-kernel weight prep: fp32 global -> fp16 swizzled smem ----
#pragma unroll
    for (int m = 0; m < 6; m++) {
        const float* wp = (m == 0) ? w_ap : (m == 1) ? w_ag : (m == 2) ? w_bp :
                          (m == 3) ? w_bg : (m == 4) ? w_g : w_z;
        const float4* src = (const float4*)wp;
#pragma unroll
        for (int i = 0; i < 4; i++) {
            int cid = t + i * NT;
            int n = cid >> 4, c8 = cid & 15;
            float4 f0 = __ldg(src + n * 32 + c8 * 2);
            float4 f1 = __ldg(src + n * 32 + c8 * 2 + 1);
            uint4 hv = make_uint4(f16x2(f0.x, f0.y), f16x2(f0.z, f0.w),
                                  f16x2(f1.x, f1.y), f16x2(f1.z, f1.w));
            uint32_t off = WSLOT(m) + (uint32_t)n * 256u +
                           (((uint32_t)c8 * 16u) ^ (((uint32_t)n & 7u) << 4));
            *(uint4*)(sm + off) = hv;
        }
    }
    if (t < 128) {
        bh[t]       = __float2half(__ldg(b_ap + t));
        bh[128 + t] = __float2half(__ldg(b_ag + t));
        bh[256 + t] = __float2half(__ldg(b_bp + t));
        bh[384 + t] = __float2half(__ldg(b_bg + t));
        bh[512 + t] = __float2half(__ldg(b_g + t));
        bh[640 + t] = __float2half(__ldg(b_z + t));
        bh[768 + t] = __float2half(__ldg(ln_out_w + t));
        bh[896 + t] = __float2half(__ldg(ln_out_b + t));
        red[t] = 0.f;
    }

    // per-warp/lane ldmatrix constants
    const uint32_t arow = (uint32_t)(wr + (lid & 15)) * 256u;
    const uint32_t l16a = (uint32_t)(lid >> 4) * 16u;
    const uint32_t axv = (uint32_t)(lid & 7) << 4;
    const int n_lane = wc + (lid & 7) + ((lid >> 4) << 3);
    const uint32_t l16 = (uint32_t)((lid >> 3) & 1) * 16u;
    const uint32_t xv = (uint32_t)(n_lane & 7) << 4;
    const uint32_t wnl = (uint32_t)n_lane * 256u;
    const uint32_t W0 = smb + WSLOT(0) + wnl, W1 = smb + WSLOT(1) + wnl;
    const uint32_t W2 = smb + WSLOT(2) + wnl, W3 = smb + WSLOT(3) + wnl;
    const uint32_t W4 = smb + WSLOT(4) + wnl, W5 = smb + WSLOT(5) + wnl;

    const int tile0 = blockIdx.x;
    if (tile0 >= ntiles) return;

    // prologue: stage first tile into buffer 0
    ln_in_tile(sm, z, mask, ln_in_w, ln_in_b, (size_t)tile0 * 64, 0u, mkh, t);
    __syncthreads();                           // S0: weights + zn[0] + bias visible

    int it = 0;
    for (int tile = tile0; tile < ntiles; tile += gridDim.x, it++) {
        const size_t row0 = (size_t)tile * 64;
        const uint32_t cur = (uint32_t)(it & 1) * 16384u;
        const uint32_t nxtb = cur ^ 16384u;
        const int ntile = tile + gridDim.x;
        __half* mkc = mkh + (it & 1) * 64;

        // L2 prefetch of next z tile
        if (ntile < ntiles) {
            const char* zp = (const char*)(z + (size_t)ntile * 64 * 128) + t * 64;
            asm volatile("prefetch.global.L2 [%0];" :: "l"(zp));
        }

        const uint32_t azn = smb + OFF_ZN + cur + arow;
        float aP[16], aG[16], bP[16], bG[16], gg[16];
        const float m0 = __half2float(mkc[r0]), m1 = __half2float(mkc[r1]);

        // ===== QUINT pass: ap, ag, bp, bg, g in one sweep over zn =====
#pragma unroll
        for (int e = 0; e < 16; e++) { aP[e] = 0.f; aG[e] = 0.f; bP[e] = 0.f; bG[e] = 0.f; gg[e] = 0.f; }
        mm_quint(aP, aG, bP, bG, gg, azn, l16a, axv, W0, W1, W2, W3, W4, l16, xv);

        // merged epilogue: a, x, gate; LN_out partial atomics
        float x[16], gate[16];
        {
            float s0 = 0.f, s20 = 0.f, s1 = 0.f, s21 = 0.f;
#pragma unroll
            for (int nb = 0; nb < 4; nb++) {
                int e = nb * 4, col = wc + nb * 8 + qt * 2;
                float2 vap = __half22float2(*(__half2*)(bh + col));
                float2 vag = __half22float2(*(__half2*)(bh + 128 + col));
                float2 vbp = __half22float2(*(__half2*)(bh + 256 + col));
                float2 vbg = __half22float2(*(__half2*)(bh + 384 + col));
                float2 vg  = __half22float2(*(__half2*)(bh + 512 + col));
                float a0 = (aP[e]   + vap.x) * sigm(aG[e]   + vag.x) * m0;
                float a1 = (aP[e+1] + vap.y) * sigm(aG[e+1] + vag.y) * m0;
                float a2 = (aP[e+2] + vap.x) * sigm(aG[e+2] + vag.x) * m1;
                float a3 = (aP[e+3] + vap.y) * sigm(aG[e+3] + vag.y) * m1;
                x[e]   = a0 * (bP[e]   + vbp.x) * m0 * sigm(bG[e]   + vbg.x);
                x[e+1] = a1 * (bP[e+1] + vbp.y) * m0 * sigm(bG[e+1] + vbg.y);
                x[e+2] = a2 * (bP[e+2] + vbp.x) * m1 * sigm(bG[e+2] + vbg.x);
                x[e+3] = a3 * (bP[e+3] + vbp.y) * m1 * sigm(bG[e+3] + vbg.y);
                s0  += x[e] + x[e+1];   s20 += x[e]*x[e] + x[e+1]*x[e+1];
                s1  += x[e+2] + x[e+3]; s21 += x[e+2]*x[e+2] + x[e+3]*x[e+3];
                gate[e]   = sigm(gg[e]   + vg.x);
                gate[e+1] = sigm(gg[e+1] + vg.y);
                gate[e+2] = sigm(gg[e+2] + vg.x);
                gate[e+3] = sigm(gg[e+3] + vg.y);
            }
            s0  += __shfl_xor_sync(~0u, s0, 1);  s0  += __shfl_xor_sync(~0u, s0, 2);
            s20 += __shfl_xor_sync(~0u, s20, 1); s20 += __shfl_xor_sync(~0u, s20, 2);
            s1  += __shfl_xor_sync(~0u, s1, 1);  s1  += __shfl_xor_sync(~0u, s1, 2);
            s21 += __shfl_xor_sync(~0u, s21, 1); s21 += __shfl_xor_sync(~0u, s21, 2);
            if (qt == 0) {
                atomicAdd(red + 2 * r0,     s0);
                atomicAdd(red + 2 * r0 + 1, s20);
                atomicAdd(red + 2 * r1,     s1);
                atomicAdd(red + 2 * r1 + 1, s21);
            }
        }
        __syncthreads();                       // S2: zn reads done; atomics drained

        // LN_out stats + xn -> zn[cur] (fp16, swizzled)
        {
            float sa = red[2*r0], sa2 = red[2*r0+1];
            float sb = red[2*r1], sb2 = red[2*r1+1];
            float mu0 = sa * (1.f / 128);
            float rs0 = rsqrtf(fmaxf(sa2 * (1.f / 128) - mu0 * mu0, 0.f) + 1e-5f);
            float mu1 = sb * (1.f / 128);
            float rs1 = rsqrtf(fmaxf(sb2 * (1.f / 128) - mu1 * mu1, 0.f) + 1e-5f);
            const uint32_t x0v = (uint32_t)(r0 & 7) << 4;
            const uint32_t x1v = (uint32_t)(r1 & 7) << 4;
#pragma unroll
            for (int nb = 0; nb < 4; nb++) {
                int e = nb * 4, col = wc + nb * 8 + qt * 2;
                float2 lw = __half22float2(*(__half2*)(bh + 768 + col));
                float2 lb = __half22float2(*(__half2*)(bh + 896 + col));
                float v0 = (x[e]   - mu0) * rs0 * lw.x + lb.x;
                float v1 = (x[e+1] - mu0) * rs0 * lw.y + lb.y;
                float v2 = (x[e+2] - mu1) * rs1 * lw.x + lb.x;
                float v3 = (x[e+3] - mu1) * rs1 * lw.y + lb.y;
                uint32_t cb = (uint32_t)col * 2u;
                *(uint32_t*)(sm + OFF_ZN + cur + (uint32_t)r0 * 256u + (cb ^ x0v)) = f16x2(v0, v1);
                *(uint32_t*)(sm + OFF_ZN + cur + (uint32_t)r1 * 256u + (cb ^ x1v)) = f16x2(v2, v3);
            }
        }
        __syncthreads();                       // S3: xn visible; red reads done
        if (t < 128) red[t] = 0.f;             // re-arm stats for next tile

        // ===== pass z: out = (xn @ w_z^T + b_z) * gate =====
        float acc[16];
#pragma unroll
        for (int e = 0; e < 16; e++) acc[e] = 0.f;
        mm1(acc, azn, l16a, axv, W5, l16, xv);
        {
            float* o0 = out + (row0 + r0) * 128;
            float* o1 = out + (row0 + r1) * 128;
#pragma unroll
            for (int nb = 0; nb < 4; nb++) {
                int e = nb * 4, col = wc + nb * 8 + qt * 2;
                float2 bz = __half22float2(*(__half2*)(bh + 640 + col));
                float2 u, v2;
                u.x  = (acc[e]   + bz.x) * gate[e];
                u.y  = (acc[e+1] + bz.y) * gate[e+1];
                v2.x = (acc[e+2] + bz.x) * gate[e+2];
                v2.y = (acc[e+3] + bz.y) * gate[e+3];
                *(float2*)(o0 + col) = u;
                *(float2*)(o1 + col) = v2;
            }
        }

        // stage next tile's zn into the other buffer (overlaps pass-z tails)
        if (ntile < ntiles)
            ln_in_tile(sm, z, mask, ln_in_w, ln_in_b, (size_t)ntile * 64, nxtb,
                       mkh + ((it + 1) & 1) * 64, t);
        __syncthreads();                       // S_end: zn[nxt] ready; red zeroed
    }
}

extern "C" void kernel_launch(void* const* d_in, const int* in_sizes, int n_in,
                              void* d_out, int out_size) {
    const float* z        = (const float*)d_in[0];
    const float* mask     = (const float*)d_in[1];
    const float* w_ap     = (const float*)d_in[2];
    const float* b_ap     = (const float*)d_in[3];
    const float* w_bp     = (const float*)d_in[4];
    const float* b_bp     = (const float*)d_in[5];
    const float* w_ag     = (const float*)d_in[6];
    const float* b_ag     = (const float*)d_in[7];
    const float* w_bg     = (const float*)d_in[8];
    const float* b_bg     = (const float*)d_in[9];
    const float* w_g      = (const float*)d_in[10];
    const float* b_g      = (const float*)d_in[11];
    const float* w_z      = (const float*)d_in[12];
    const float* b_z      = (const float*)d_in[13];
    const float* ln_in_w  = (const float*)d_in[14];
    const float* ln_in_b  = (const float*)d_in[15];
    const float* ln_out_w = (const float*)d_in[16];
    const float* ln_out_b = (const float*)d_in[17];
    float* out = (float*)d_out;

    const int rows = in_sizes[1];      // B*N*N
    const int ntiles = rows / 64;      // 2304

    static int nsm = 0;
    if (!nsm) {
        cudaFuncSetAttribute(tmu_kernel, cudaFuncAttributeMaxDynamicSharedMemorySize, SMEM_BYTES);
        if (cudaDeviceGetAttribute(&nsm, cudaDevAttrMultiProcessorCount, 0) != cudaSuccess || nsm <= 0)
            nsm = 148;
    }
    int grid = nsm < ntiles ? nsm : ntiles;

    tmu_kernel<<<grid, NT, SMEM_BYTES>>>(z, mask,
                                         w_ap, b_ap, w_bp, b_bp,
                                         w_ag, b_ag, w_bg, b_bg,
                                         w_g, b_g, w_z, b_z,
                                         ln_in_w, ln_in_b, ln_out_w, ln_out_b,
                                         out, ntiles);
}

// round 16
// speedup vs baseline: 1.3655x; 1.2733x over previous
#include <cuda_runtime.h>
#include <cuda_fp16.h>
#include <stdint.h>

// TriangleMultiplicativeUpdate — persistent single-launch kernel, round 15.
// R14 chassis (six fp16 weights resident in smem, in-kernel conversion,
// double-buffered zn, 64-row tiles, quint fused pass) plus:
//  * sigmoid via ex2.approx + rcp.approx (pins fast approx math regardless of
//    compiler flags; avoids a possible div.rn.f32 software sequence)
//  * ln_in w/b cached in smem fp16 (exact for 1/0), removing 32 LDG per
//    thread per tile from the serial LN_in path; ln_out params via __ldg.

#define NT 512

#define OFF_ZN   0u                 // zn/xn: 2 x (64 x 256B fp16, swizzled)
#define OFF_W0   32768u             // 6 weight slots, 32768B each, swizzled
#define WSLOT(i) (OFF_W0 + (uint32_t)(i) * 32768u)
#define OFF_SB   229376u            // 8 x 128 __half (6 biases, ln_in w/b)
#define OFF_MK   231424u            // 2 x 64 __half (mask per buffer)
#define OFF_RED  231680u            // 64 x float2 (LN_out partials, atomics)
#define SMEM_BYTES 232192

__device__ __forceinline__ uint32_t s2u(const void* p) {
    uint32_t a;
    asm("{ .reg .u64 t; cvta.to.shared.u64 t, %1; cvt.u32.u64 %0, t; }" : "=r"(a) : "l"(p));
    return a;
}
__device__ __forceinline__ uint32_t f16x2(float lo, float hi) {
    uint32_t r;
    asm("cvt.rn.f16x2.f32 %0, %1, %2;" : "=r"(r) : "f"(hi), "f"(lo));
    return r;
}

#define LDSM4(r, a) \
    asm volatile("ldmatrix.sync.aligned.m8n8.x4.shared.b16 {%0,%1,%2,%3}, [%4];" \
        : "=r"((r)[0]), "=r"((r)[1]), "=r"((r)[2]), "=r"((r)[3]) : "r"(a))

#define MMAOP(d, a, b0, b1) \
    asm volatile("mma.sync.aligned.m16n8k16.row.col.f32.f16.f16.f32 " \
        "{%0,%1,%2,%3}, {%4,%5,%6,%7}, {%8,%9}, {%0,%1,%2,%3};" \
        : "+f"((d)[0]), "+f"((d)[1]), "+f"((d)[2]), "+f"((d)[3]) \
        : "r"((a)[0]), "r"((a)[1]), "r"((a)[2]), "r"((a)[3]), "r"(b0), "r"(b1))

// sigmoid with pinned approx ops: ex2-based exp + rcp.approx (2 MUFU + adds)
__device__ __forceinline__ float sigm(float x) {
    float e = __expf(-x);
    float d = 1.0f + e;
    float r;
    asm("rcp.approx.f32 %0, %1;" : "=f"(r) : "f"(d));
    return r;
}

// single pass: acc[16] += A(16x128) @ W^T (32 cols); swizzled operands.
__device__ __forceinline__ void mm1(float* acc, uint32_t azn, uint32_t l16a, uint32_t axv,
                                    uint32_t wb, uint32_t l16, uint32_t xv) {
#pragma unroll
    for (int k = 0; k < 8; k++) {
        uint32_t ko = (uint32_t)k * 32u;
        uint32_t offa = (ko + l16a) ^ axv;
        uint32_t offb = (ko + l16) ^ xv;
        uint32_t A[4], B0[4], B1[4];
        LDSM4(A, azn + offa);
        LDSM4(B0, wb + offb);
        LDSM4(B1, wb + offb + 4096u);
        MMAOP(acc + 0,  A, B0[0], B0[1]); MMAOP(acc + 4,  A, B0[2], B0[3]);
        MMAOP(acc + 8,  A, B1[0], B1[1]); MMAOP(acc + 12, A, B1[2], B1[3]);
    }
}

// quint pass: 5 accumulator sets against 5 weights, A loaded ONCE per k-step.
__device__ __forceinline__ void mm_quint(float* a0, float* a1, float* a2,
                                         float* a3, float* a4,
                                         uint32_t azn, uint32_t l16a, uint32_t axv,
                                         uint32_t w0, uint32_t w1, uint32_t w2,
                                         uint32_t w3, uint32_t w4,
                                         uint32_t l16, uint32_t xv) {
#pragma unroll
    for (int k = 0; k < 8; k++) {
        uint32_t ko = (uint32_t)k * 32u;
        uint32_t offa = (ko + l16a) ^ axv;
        uint32_t offb = (ko + l16) ^ xv;
        uint32_t A[4];
        LDSM4(A, azn + offa);
        {
            uint32_t B0[4], B1[4];
            LDSM4(B0, w0 + offb); LDSM4(B1, w0 + offb + 4096u);
            MMAOP(a0 + 0,  A, B0[0], B0[1]); MMAOP(a0 + 4,  A, B0[2], B0[3]);
            MMAOP(a0 + 8,  A, B1[0], B1[1]); MMAOP(a0 + 12, A, B1[2], B1[3]);
        }
        {
            uint32_t B0[4], B1[4];
            LDSM4(B0, w1 + offb); LDSM4(B1, w1 + offb + 4096u);
            MMAOP(a1 + 0,  A, B0[0], B0[1]); MMAOP(a1 + 4,  A, B0[2], B0[3]);
            MMAOP(a1 + 8,  A, B1[0], B1[1]); MMAOP(a1 + 12, A, B1[2], B1[3]);
        }
        {
            uint32_t B0[4], B1[4];
            LDSM4(B0, w2 + offb); LDSM4(B1, w2 + offb + 4096u);
            MMAOP(a2 + 0,  A, B0[0], B0[1]); MMAOP(a2 + 4,  A, B0[2], B0[3]);
            MMAOP(a2 + 8,  A, B1[0], B1[1]); MMAOP(a2 + 12, A, B1[2], B1[3]);
        }
        {
            uint32_t B0[4], B1[4];
            LDSM4(B0, w3 + offb); LDSM4(B1, w3 + offb + 4096u);
            MMAOP(a3 + 0,  A, B0[0], B0[1]); MMAOP(a3 + 4,  A, B0[2], B0[3]);
            MMAOP(a3 + 8,  A, B1[0], B1[1]); MMAOP(a3 + 12, A, B1[2], B1[3]);
        }
        {
            uint32_t B0[4], B1[4];
            LDSM4(B0, w4 + offb); LDSM4(B1, w4 + offb + 4096u);
            MMAOP(a4 + 0,  A, B0[0], B0[1]); MMAOP(a4 + 4,  A, B0[2], B0[3]);
            MMAOP(a4 + 8,  A, B1[0], B1[1]); MMAOP(a4 + 12, A, B1[2], B1[3]);
        }
    }
}

// LN_in for one 64-row tile into zn buffer `bufoff`; 8 threads/row.
// ln_in w/b read from smem fp16 cache (bh rows 6,7).
__device__ __forceinline__ void ln_in_tile(char* sm, const float* z,
                                           const float* mask,
                                           const __half* bh,
                                           size_t row0, uint32_t bufoff,
                                           __half* mkh, int t) {
    const int r = t >> 3, q = t & 7;
    const uint32_t rxv = (uint32_t)(r & 7) << 4;
    const float* zr = z + (row0 + r) * 128 + q * 16;
    float v[16], s = 0.f, s2 = 0.f;
#pragma unroll
    for (int i = 0; i < 4; i++) {
        float4 f = __ldg((const float4*)(zr + 4 * i));
        v[4*i] = f.x; v[4*i+1] = f.y; v[4*i+2] = f.z; v[4*i+3] = f.w;
        s += f.x + f.y + f.z + f.w;
        s2 += f.x*f.x + f.y*f.y + f.z*f.z + f.w*f.w;
    }
    s  += __shfl_xor_sync(~0u, s, 1);  s  += __shfl_xor_sync(~0u, s, 2);
    s  += __shfl_xor_sync(~0u, s, 4);
    s2 += __shfl_xor_sync(~0u, s2, 1); s2 += __shfl_xor_sync(~0u, s2, 2);
    s2 += __shfl_xor_sync(~0u, s2, 4);
    float mu = s * (1.f / 128);
    float rstd = rsqrtf(fmaxf(s2 * (1.f / 128) - mu * mu, 0.f) + 1e-5f);
#pragma unroll
    for (int j = 0; j < 2; j++) {
        uint32_t h[4];
#pragma unroll
        for (int i = 0; i < 4; i++) {
            int c = q * 16 + j * 8 + i * 2;
            float2 lw = __half22float2(*(const __half2*)(bh + 768 + c));
            float2 lb = __half22float2(*(const __half2*)(bh + 896 + c));
            float f0 = (v[j*8+i*2]   - mu) * rstd * lw.x + lb.x;
            float f1 = (v[j*8+i*2+1] - mu) * rstd * lw.y + lb.y;
            h[i] = f16x2(f0, f1);
        }
        uint32_t o = ((uint32_t)(q * 2 + j) * 16u) ^ rxv;
        *(uint4*)(sm + OFF_ZN + bufoff + (uint32_t)r * 256u + o) =
            make_uint4(h[0], h[1], h[2], h[3]);
    }
    if (q == 0) mkh[r] = __float2half(__ldg(mask + row0 + r));
}

__global__ void __launch_bounds__(NT, 1)
tmu_kernel(const float* __restrict__ z, const float* __restrict__ mask,
           const float* __restrict__ w_ap, const float* __restrict__ b_ap,
           const float* __restrict__ w_bp, const float* __restrict__ b_bp,
           const float* __restrict__ w_ag, const float* __restrict__ b_ag,
           const float* __restrict__ w_bg, const float* __restrict__ b_bg,
           const float* __restrict__ w_g,  const float* __restrict__ b_g,
           const float* __restrict__ w_z,  const float* __restrict__ b_z,
           const float* __restrict__ ln_in_w,  const float* __restrict__ ln_in_b,
           const float* __restrict__ ln_out_w, const float* __restrict__ ln_out_b,
           float* __restrict__ out, int ntiles) {
    extern __shared__ char sm[];
    const uint32_t smb = s2u(sm);
    const int t = threadIdx.x;
    const int w = t >> 5, lid = t & 31;
    const int quad = lid >> 2, qt = lid & 3;
    const int wr = (w & 3) * 16;
    const int wc = (w >> 2) * 32;
    const int r0 = wr + quad, r1 = r0 + 8;

    __half* bh  = (__half*)(sm + OFF_SB);
    __half* mkh = (__half*)(sm + OFF_MK);
    float*  red = (float*)(sm + OFF_RED);    // [64][2] sum, sumsq

    // ---- in-kernel weight prep: fp32 global -> fp16 swizzled smem ----
#pragma unroll
    for (int m = 0; m < 6; m++) {
        const float* wp = (m == 0) ? w_ap : (m == 1) ? w_ag : (m == 2) ? w_bp :
                          (m == 3) ? w_bg : (m == 4) ? w_g : w_z;
        const float4* src = (const float4*)wp;
#pragma unroll
        for (int i = 0; i < 4; i++) {
            int cid = t + i * NT;
            int n = cid >> 4, c8 = cid & 15;
            float4 f0 = __ldg(src + n * 32 + c8 * 2);
            float4 f1 = __ldg(src + n * 32 + c8 * 2 + 1);
            uint4 hv = make_uint4(f16x2(f0.x, f0.y), f16x2(f0.z, f0.w),
                                  f16x2(f1.x, f1.y), f16x2(f1.z, f1.w));
            uint32_t off = WSLOT(m) + (uint32_t)n * 256u +
                           (((uint32_t)c8 * 16u) ^ (((uint32_t)n & 7u) << 4));
            *(uint4*)(sm + off) = hv;
        }
    }
    if (t < 128) {
        bh[t]       = __float2half(__ldg(b_ap + t));
        bh[128 + t] = __float2half(__ldg(b_ag + t));
        bh[256 + t] = __float2half(__ldg(b_bp + t));
        bh[384 + t] = __float2half(__ldg(b_bg + t));
        bh[512 + t] = __float2half(__ldg(b_g + t));
        bh[640 + t] = __float2half(__ldg(b_z + t));
        bh[768 + t] = __float2half(__ldg(ln_in_w + t));   // ln_in cached fp16
        bh[896 + t] = __float2half(__ldg(ln_in_b + t));
        red[t] = 0.f;
    }

    // per-warp/lane ldmatrix constants
    const uint32_t arow = (uint32_t)(wr + (lid & 15)) * 256u;
    const uint32_t l16a = (uint32_t)(lid >> 4) * 16u;
    const uint32_t axv = (uint32_t)(lid & 7) << 4;
    const int n_lane = wc + (lid & 7) + ((lid >> 4) << 3);
    const uint32_t l16 = (uint32_t)((lid >> 3) & 1) * 16u;
    const uint32_t xv = (uint32_t)(n_lane & 7) << 4;
    const uint32_t wnl = (uint32_t)n_lane * 256u;
    const uint32_t W0 = smb + WSLOT(0) + wnl, W1 = smb + WSLOT(1) + wnl;
    const uint32_t W2 = smb + WSLOT(2) + wnl, W3 = smb + WSLOT(3) + wnl;
    const uint32_t W4 = smb + WSLOT(4) + wnl, W5 = smb + WSLOT(5) + wnl;

    const int tile0 = blockIdx.x;
    if (tile0 >= ntiles) return;

    __syncthreads();                           // bh (ln_in cache) visible for LN

    // prologue: stage first tile into buffer 0
    ln_in_tile(sm, z, mask, bh, (size_t)tile0 * 64, 0u, mkh, t);
    __syncthreads();                           // S0: weights + zn[0] visible

    int it = 0;
    for (int tile = tile0; tile < ntiles; tile += gridDim.x, it++) {
        const size_t row0 = (size_t)tile * 64;
        const uint32_t cur = (uint32_t)(it & 1) * 16384u;
        const uint32_t nxtb = cur ^ 16384u;
        const int ntile = tile + gridDim.x;
        __half* mkc = mkh + (it & 1) * 64;

        // L2 prefetch of next z tile
        if (ntile < ntiles) {
            const char* zp = (const char*)(z + (size_t)ntile * 64 * 128) + t * 64;
            asm volatile("prefetch.global.L2 [%0];" :: "l"(zp));
        }

        const uint32_t azn = smb + OFF_ZN + cur + arow;
        float aP[16], aG[16], bP[16], bG[16], gg[16];
        const float m0 = __half2float(mkc[r0]), m1 = __half2float(mkc[r1]);

        // ===== QUINT pass: ap, ag, bp, bg, g in one sweep over zn =====
#pragma unroll
        for (int e = 0; e < 16; e++) { aP[e] = 0.f; aG[e] = 0.f; bP[e] = 0.f; bG[e] = 0.f; gg[e] = 0.f; }
        mm_quint(aP, aG, bP, bG, gg, azn, l16a, axv, W0, W1, W2, W3, W4, l16, xv);

        // merged epilogue: a, x, gate; LN_out partial atomics
        float x[16], gate[16];
        {
            float s0 = 0.f, s20 = 0.f, s1 = 0.f, s21 = 0.f;
#pragma unroll
            for (int nb = 0; nb < 4; nb++) {
                int e = nb * 4, col = wc + nb * 8 + qt * 2;
                float2 vap = __half22float2(*(__half2*)(bh + col));
                float2 vag = __half22float2(*(__half2*)(bh + 128 + col));
                float2 vbp = __half22float2(*(__half2*)(bh + 256 + col));
                float2 vbg = __half22float2(*(__half2*)(bh + 384 + col));
                float2 vg  = __half22float2(*(__half2*)(bh + 512 + col));
                float a0 = (aP[e]   + vap.x) * sigm(aG[e]   + vag.x) * m0;
                float a1 = (aP[e+1] + vap.y) * sigm(aG[e+1] + vag.y) * m0;
                float a2 = (aP[e+2] + vap.x) * sigm(aG[e+2] + vag.x) * m1;
                float a3 = (aP[e+3] + vap.y) * sigm(aG[e+3] + vag.y) * m1;
                x[e]   = a0 * (bP[e]   + vbp.x) * m0 * sigm(bG[e]   + vbg.x);
                x[e+1] = a1 * (bP[e+1] + vbp.y) * m0 * sigm(bG[e+1] + vbg.y);
                x[e+2] = a2 * (bP[e+2] + vbp.x) * m1 * sigm(bG[e+2] + vbg.x);
                x[e+3] = a3 * (bP[e+3] + vbp.y) * m1 * sigm(bG[e+3] + vbg.y);
                s0  += x[e] + x[e+1];   s20 += x[e]*x[e] + x[e+1]*x[e+1];
                s1  += x[e+2] + x[e+3]; s21 += x[e+2]*x[e+2] + x[e+3]*x[e+3];
                gate[e]   = sigm(gg[e]   + vg.x);
                gate[e+1] = sigm(gg[e+1] + vg.y);
                gate[e+2] = sigm(gg[e+2] + vg.x);
                gate[e+3] = sigm(gg[e+3] + vg.y);
            }
            s0  += __shfl_xor_sync(~0u, s0, 1);  s0  += __shfl_xor_sync(~0u, s0, 2);
            s20 += __shfl_xor_sync(~0u, s20, 1); s20 += __shfl_xor_sync(~0u, s20, 2);
            s1  += __shfl_xor_sync(~0u, s1, 1);  s1  += __shfl_xor_sync(~0u, s1, 2);
            s21 += __shfl_xor_sync(~0u, s21, 1); s21 += __shfl_xor_sync(~0u, s21, 2);
            if (qt == 0) {
                atomicAdd(red + 2 * r0,     s0);
                atomicAdd(red + 2 * r0 + 1, s20);
                atomicAdd(red + 2 * r1,     s1);
                atomicAdd(red + 2 * r1 + 1, s21);
            }
        }
        __syncthreads();                       // S2: zn reads done; atomics drained

        // LN_out stats + xn -> zn[cur] (fp16, swizzled); ln_out via __ldg
        {
            float sa = red[2*r0], sa2 = red[2*r0+1];
            float sb = red[2*r1], sb2 = red[2*r1+1];
            float mu0 = sa * (1.f / 128);
            float rs0 = rsqrtf(fmaxf(sa2 * (1.f / 128) - mu0 * mu0, 0.f) + 1e-5f);
            float mu1 = sb * (1.f / 128);
            float rs1 = rsqrtf(fmaxf(sb2 * (1.f / 128) - mu1 * mu1, 0.f) + 1e-5f);
            const uint32_t x0v = (uint32_t)(r0 & 7) << 4;
            const uint32_t x1v = (uint32_t)(r1 & 7) << 4;
#pragma unroll
            for (int nb = 0; nb < 4; nb++) {
                int e = nb * 4, col = wc + nb * 8 + qt * 2;
                float2 lw = __ldg((const float2*)(ln_out_w + col));
                float2 lb = __ldg((const float2*)(ln_out_b + col));
                float v0 = (x[e]   - mu0) * rs0 * lw.x + lb.x;
                float v1 = (x[e+1] - mu0) * rs0 * lw.y + lb.y;
                float v2 = (x[e+2] - mu1) * rs1 * lw.x + lb.x;
                float v3 = (x[e+3] - mu1) * rs1 * lw.y + lb.y;
                uint32_t cb = (uint32_t)col * 2u;
                *(uint32_t*)(sm + OFF_ZN + cur + (uint32_t)r0 * 256u + (cb ^ x0v)) = f16x2(v0, v1);
                *(uint32_t*)(sm + OFF_ZN + cur + (uint32_t)r1 * 256u + (cb ^ x1v)) = f16x2(v2, v3);
            }
        }
        __syncthreads();                       // S3: xn visible; red reads done
        if (t < 128) red[t] = 0.f;             // re-arm stats for next tile

        // ===== pass z: out = (xn @ w_z^T + b_z) * gate =====
        float acc[16];
#pragma unroll
        for (int e = 0; e < 16; e++) acc[e] = 0.f;
        mm1(acc, azn, l16a, axv, W5, l16, xv);
        {
            float* o0 = out + (row0 + r0) * 128;
            float* o1 = out + (row0 + r1) * 128;
#pragma unroll
            for (int nb = 0; nb < 4; nb++) {
                int e = nb * 4, col = wc + nb * 8 + qt * 2;
                float2 bz = __half22float2(*(__half2*)(bh + 640 + col));
                float2 u, v2;
                u.x  = (acc[e]   + bz.x) * gate[e];
                u.y  = (acc[e+1] + bz.y) * gate[e+1];
                v2.x = (acc[e+2] + bz.x) * gate[e+2];
                v2.y = (acc[e+3] + bz.y) * gate[e+3];
                *(float2*)(o0 + col) = u;
                *(float2*)(o1 + col) = v2;
            }
        }

        // stage next tile's zn into the other buffer (overlaps pass-z tails)
        if (ntile < ntiles)
            ln_in_tile(sm, z, mask, bh, (size_t)ntile * 64, nxtb,
                       mkh + ((it + 1) & 1) * 64, t);
        __syncthreads();                       // S_end: zn[nxt] ready; red zeroed
    }
}

extern "C" void kernel_launch(void* const* d_in, const int* in_sizes, int n_in,
                              void* d_out, int out_size) {
    const float* z        = (const float*)d_in[0];
    const float* mask     = (const float*)d_in[1];
    const float* w_ap     = (const float*)d_in[2];
    const float* b_ap     = (const float*)d_in[3];
    const float* w_bp     = (const float*)d_in[4];
    const float* b_bp     = (const float*)d_in[5];
    const float* w_ag     = (const float*)d_in[6];
    const float* b_ag     = (const float*)d_in[7];
    const float* w_bg     = (const float*)d_in[8];
    const float* b_bg     = (const float*)d_in[9];
    const float* w_g      = (const float*)d_in[10];
    const float* b_g      = (const float*)d_in[11];
    const float* w_z      = (const float*)d_in[12];
    const float* b_z      = (const float*)d_in[13];
    const float* ln_in_w  = (const float*)d_in[14];
    const float* ln_in_b  = (const float*)d_in[15];
    const float* ln_out_w = (const float*)d_in[16];
    const float* ln_out_b = (const float*)d_in[17];
    float* out = (float*)d_out;

    const int rows = in_sizes[1];      // B*N*N
    const int ntiles = rows / 64;      // 2304

    static int nsm = 0;
    if (!nsm) {
        cudaFuncSetAttribute(tmu_kernel, cudaFuncAttributeMaxDynamicSharedMemorySize, SMEM_BYTES);
        if (cudaDeviceGetAttribute(&nsm, cudaDevAttrMultiProcessorCount, 0) != cudaSuccess || nsm <= 0)
            nsm = 148;
    }
    int grid = nsm < ntiles ? nsm : ntiles;

    tmu_kernel<<<grid, NT, SMEM_BYTES>>>(z, mask,
                                         w_ap, b_ap, w_bp, b_bp,
                                         w_ag, b_ag, w_bg, b_bg,
                                         w_g, b_g, w_z, b_z,
                                         ln_in_w, ln_in_b, ln_out_w, ln_out_b,
                                         out, ntiles);
}